// round 2
// baseline (speedup 1.0000x reference)
#include <cuda_runtime.h>
#include <cuda_bf16.h>
#include <stdint.h>

// ---------------------------------------------------------------------------
// GraphConv: out = SpMM(adj, x@W + lin_bias) + bias
// Inputs (metadata order): x[100000,128] f32, W[128,128] f32, lin_bias[128] f32,
//   bias[128] f32, adj_rows[E] i32, adj_cols[E] i32, adj_vals[E] f32
// Output: out[100000,128] f32
// ---------------------------------------------------------------------------

#define D 128            // D_IN == D_OUT == 128
#define TK 64            // K-chunk
#define PADX 69          // xs row stride: 8*69 % 32 == 8 -> conflict-free frag loads

// scratch for support = x@W + lin_bias  (51.2 MB)
__device__ float g_support[100000 * D];

// ---------------------------------------------------------------------------
// Kernel 1: support = x @ W + lin_bias
// Block tile 128x128, 256 threads, 8x8 register tile per thread, K chunked by 64.
// ---------------------------------------------------------------------------
__global__ void __launch_bounds__(256, 2)
gemm_kernel(const float* __restrict__ x, const float* __restrict__ W,
            const float* __restrict__ lin_bias, float* __restrict__ sup, int M)
{
    extern __shared__ float sh[];
    float* xs = sh;                 // [128][PADX]
    float* Ws = sh + 128 * PADX;    // [TK][128]

    const int tid  = threadIdx.x;
    const int warp = tid >> 5;
    const int lane = tid & 31;
    const int lr = lane >> 3;       // 0..3
    const int lc = lane & 7;        // 0..7
    const int wr = warp & 3;        // 0..3  (row warps)
    const int wc = warp >> 2;       // 0..1  (col warps)

    const int rowBase = blockIdx.x * 128;
    const int row0 = wr * 32 + lr * 8;       // local row of this thread's 8 rows
    const int col0 = wc * 64 + lc * 8;       // local col of this thread's 8 cols

    float acc[8][8];
#pragma unroll
    for (int r = 0; r < 8; r++)
#pragma unroll
        for (int c = 0; c < 8; c++) acc[r][c] = 0.f;

    for (int k0 = 0; k0 < D; k0 += TK) {
        // stage x tile: 128 rows x TK cols (float4 loads, scalar smem stores)
        for (int i = tid; i < 128 * (TK / 4); i += 256) {
            int m  = i / (TK / 4);
            int kq = (i % (TK / 4)) * 4;
            int gm = rowBase + m;
            float4 v = make_float4(0.f, 0.f, 0.f, 0.f);
            if (gm < M) v = *(const float4*)(x + (size_t)gm * D + k0 + kq);
            float* dst = xs + m * PADX + kq;
            dst[0] = v.x; dst[1] = v.y; dst[2] = v.z; dst[3] = v.w;
        }
        // stage W chunk: TK x 128
        for (int i = tid; i < TK * (D / 4); i += 256) {
            int kk = i / (D / 4);
            int n4 = (i % (D / 4)) * 4;
            *(float4*)(Ws + kk * D + n4) =
                *(const float4*)(W + (size_t)(k0 + kk) * D + n4);
        }
        __syncthreads();

#pragma unroll 8
        for (int k = 0; k < TK; k++) {
            float a[8], b[8];
#pragma unroll
            for (int r = 0; r < 8; r++) a[r] = xs[(row0 + r) * PADX + k];
            float4 b0 = *(float4*)(Ws + k * D + col0);
            float4 b1 = *(float4*)(Ws + k * D + col0 + 4);
            b[0] = b0.x; b[1] = b0.y; b[2] = b0.z; b[3] = b0.w;
            b[4] = b1.x; b[5] = b1.y; b[6] = b1.z; b[7] = b1.w;
#pragma unroll
            for (int r = 0; r < 8; r++)
#pragma unroll
                for (int c = 0; c < 8; c++) acc[r][c] += a[r] * b[c];
        }
        __syncthreads();
    }

    // epilogue: + lin_bias, store
    float4 lb0 = *(const float4*)(lin_bias + col0);
    float4 lb1 = *(const float4*)(lin_bias + col0 + 4);
#pragma unroll
    for (int r = 0; r < 8; r++) {
        int gm = rowBase + row0 + r;
        if (gm < M) {
            float4 o0, o1;
            o0.x = acc[r][0] + lb0.x; o0.y = acc[r][1] + lb0.y;
            o0.z = acc[r][2] + lb0.z; o0.w = acc[r][3] + lb0.w;
            o1.x = acc[r][4] + lb1.x; o1.y = acc[r][5] + lb1.y;
            o1.z = acc[r][6] + lb1.z; o1.w = acc[r][7] + lb1.w;
            float* dst = sup + (size_t)gm * D + col0;
            *(float4*)dst       = o0;
            *(float4*)(dst + 4) = o1;
        }
    }
}

// ---------------------------------------------------------------------------
// Kernel 2: out[n][d] = bias[d]   (full overwrite; d_out is poisoned)
// ---------------------------------------------------------------------------
__global__ void init_kernel(float* __restrict__ out, const float* __restrict__ bias, int M)
{
    int total = M * (D / 4);
    float4 b[ D / 4 / 8 ];  // not used; simple path below
    (void)b;
    for (int i = blockIdx.x * blockDim.x + threadIdx.x; i < total;
         i += gridDim.x * blockDim.x) {
        int d4 = i & (D / 4 - 1);          // D/4 = 32 (power of 2)
        float4 v = *(const float4*)(bias + d4 * 4);
        ((float4*)out)[i] = v;
    }
}

// ---------------------------------------------------------------------------
// Kernel 3: scatter-add. One warp per edge: gather support[col] (float4/lane),
// scale by val, atomicAdd (REDG) into out[row].
// ---------------------------------------------------------------------------
__global__ void __launch_bounds__(256)
spmm_kernel(const float* __restrict__ sup,
            const int* __restrict__ rows, const int* __restrict__ cols,
            const float* __restrict__ vals, float* __restrict__ out, int nE)
{
    int e = blockIdx.x * 8 + (threadIdx.x >> 5);
    if (e >= nE) return;
    int lane = threadIdx.x & 31;

    int r   = __ldg(rows + e);
    int c   = __ldg(cols + e);
    float v = __ldg(vals + e);

    float4 s = *(const float4*)(sup + (size_t)c * D + lane * 4);
    float* o = out + (size_t)r * D + lane * 4;
    atomicAdd(o + 0, v * s.x);
    atomicAdd(o + 1, v * s.y);
    atomicAdd(o + 2, v * s.z);
    atomicAdd(o + 3, v * s.w);
}

// ---------------------------------------------------------------------------
extern "C" void kernel_launch(void* const* d_in, const int* in_sizes, int n_in,
                              void* d_out, int out_size)
{
    const float* x        = (const float*)d_in[0];
    const float* W        = (const float*)d_in[1];
    const float* lin_bias = (const float*)d_in[2];
    const float* bias     = (const float*)d_in[3];
    const int*   adj_rows = (const int*)d_in[4];
    const int*   adj_cols = (const int*)d_in[5];
    const float* adj_vals = (const float*)d_in[6];
    float* out = (float*)d_out;

    const int M  = in_sizes[0] / D;      // 100000
    const int nE = in_sizes[4];          // 1600000

    float* sup = nullptr;
    cudaGetSymbolAddress((void**)&sup, g_support);

    const int smem = (128 * PADX + TK * D) * sizeof(float);  // ~68 KB
    cudaFuncSetAttribute(gemm_kernel, cudaFuncAttributeMaxDynamicSharedMemorySize, smem);

    // 1) support = x@W + lin_bias
    int gemmGrid = (M + 127) / 128;
    gemm_kernel<<<gemmGrid, 256, smem>>>(x, W, lin_bias, sup, M);

    // 2) out = bias (broadcast)
    init_kernel<<<1024, 256>>>(out, bias, M);

    // 3) out[r] += vals[e] * support[cols[e]]
    int spmmGrid = (nE + 7) / 8;
    spmm_kernel<<<spmmGrid, 256>>>(sup, adj_rows, adj_cols, adj_vals, out, nE);
}

// round 4
// speedup vs baseline: 1.7884x; 1.7884x over previous
#include <cuda_runtime.h>
#include <cuda_bf16.h>
#include <stdint.h>

// ---------------------------------------------------------------------------
// GraphConv: out = SpMM(adj, x@W + lin_bias) + bias
// Inputs: x[100000,128] f32, W[128,128] f32, lin_bias[128] f32, bias[128] f32,
//         adj_rows[E] i32, adj_cols[E] i32, adj_vals[E] f32
// Output: out[100000,128] f32
// ---------------------------------------------------------------------------

#define D 128            // D_IN == D_OUT == 128
#define TK 64            // K-chunk
#define PADX 69          // xs row stride: 8*69 % 32 == 8 -> conflict-free frag loads

// scratch for support = x@W + lin_bias  (51.2 MB)
__device__ float g_support[100000 * D];

// ---------------------------------------------------------------------------
// Kernel 1: support = x @ W + lin_bias  (at scalar-FFMA roofline, ~88us)
// ---------------------------------------------------------------------------
__global__ void __launch_bounds__(256, 2)
gemm_kernel(const float* __restrict__ x, const float* __restrict__ W,
            const float* __restrict__ lin_bias, float* __restrict__ sup, int M)
{
    extern __shared__ float sh[];
    float* xs = sh;                 // [128][PADX]
    float* Ws = sh + 128 * PADX;    // [TK][128]

    const int tid  = threadIdx.x;
    const int warp = tid >> 5;
    const int lane = tid & 31;
    const int lr = lane >> 3;       // 0..3
    const int lc = lane & 7;        // 0..7
    const int wr = warp & 3;        // 0..3
    const int wc = warp >> 2;       // 0..1

    const int rowBase = blockIdx.x * 128;
    const int row0 = wr * 32 + lr * 8;
    const int col0 = wc * 64 + lc * 8;

    float acc[8][8];
#pragma unroll
    for (int r = 0; r < 8; r++)
#pragma unroll
        for (int c = 0; c < 8; c++) acc[r][c] = 0.f;

    for (int k0 = 0; k0 < D; k0 += TK) {
        for (int i = tid; i < 128 * (TK / 4); i += 256) {
            int m  = i / (TK / 4);
            int kq = (i % (TK / 4)) * 4;
            int gm = rowBase + m;
            float4 v = make_float4(0.f, 0.f, 0.f, 0.f);
            if (gm < M) v = *(const float4*)(x + (size_t)gm * D + k0 + kq);
            float* dst = xs + m * PADX + kq;
            dst[0] = v.x; dst[1] = v.y; dst[2] = v.z; dst[3] = v.w;
        }
        for (int i = tid; i < TK * (D / 4); i += 256) {
            int kk = i / (D / 4);
            int n4 = (i % (D / 4)) * 4;
            *(float4*)(Ws + kk * D + n4) =
                *(const float4*)(W + (size_t)(k0 + kk) * D + n4);
        }
        __syncthreads();

#pragma unroll 8
        for (int k = 0; k < TK; k++) {
            float a[8], b[8];
#pragma unroll
            for (int r = 0; r < 8; r++) a[r] = xs[(row0 + r) * PADX + k];
            float4 b0 = *(float4*)(Ws + k * D + col0);
            float4 b1 = *(float4*)(Ws + k * D + col0 + 4);
            b[0] = b0.x; b[1] = b0.y; b[2] = b0.z; b[3] = b0.w;
            b[4] = b1.x; b[5] = b1.y; b[6] = b1.z; b[7] = b1.w;
#pragma unroll
            for (int r = 0; r < 8; r++)
#pragma unroll
                for (int c = 0; c < 8; c++) acc[r][c] += a[r] * b[c];
        }
        __syncthreads();
    }

    float4 lb0 = *(const float4*)(lin_bias + col0);
    float4 lb1 = *(const float4*)(lin_bias + col0 + 4);
#pragma unroll
    for (int r = 0; r < 8; r++) {
        int gm = rowBase + row0 + r;
        if (gm < M) {
            float4 o0, o1;
            o0.x = acc[r][0] + lb0.x; o0.y = acc[r][1] + lb0.y;
            o0.z = acc[r][2] + lb0.z; o0.w = acc[r][3] + lb0.w;
            o1.x = acc[r][4] + lb1.x; o1.y = acc[r][5] + lb1.y;
            o1.z = acc[r][6] + lb1.z; o1.w = acc[r][7] + lb1.w;
            float* dst = sup + (size_t)gm * D + col0;
            *(float4*)dst       = o0;
            *(float4*)(dst + 4) = o1;
        }
    }
}

// ---------------------------------------------------------------------------
// Kernel 2: out[n][d] = bias[d]
// ---------------------------------------------------------------------------
__global__ void init_kernel(float* __restrict__ out, const float* __restrict__ bias, int M)
{
    int total = M * (D / 4);
    for (int i = blockIdx.x * blockDim.x + threadIdx.x; i < total;
         i += gridDim.x * blockDim.x) {
        int d4 = i & (D / 4 - 1);
        float4 v = *(const float4*)(bias + d4 * 4);
        ((float4*)out)[i] = v;
    }
}

// ---------------------------------------------------------------------------
// Kernel 3: scatter-add, warp per edge, ONE red.global.add.v4.f32 per lane
// (4x fewer REDG lane-ops than 4 scalar atomicAdds).
// ---------------------------------------------------------------------------
__device__ __forceinline__ void red_add_v4(float* addr, float4 v)
{
    asm volatile("red.global.add.v4.f32 [%0], {%1, %2, %3, %4};"
                 :: "l"(addr), "f"(v.x), "f"(v.y), "f"(v.z), "f"(v.w)
                 : "memory");
}

__global__ void __launch_bounds__(256)
spmm_kernel(const float* __restrict__ sup,
            const int* __restrict__ rows, const int* __restrict__ cols,
            const float* __restrict__ vals, float* __restrict__ out, int nE)
{
    int e = blockIdx.x * 8 + (threadIdx.x >> 5);
    if (e >= nE) return;
    int lane = threadIdx.x & 31;

    int r   = __ldg(rows + e);
    int c   = __ldg(cols + e);
    float v = __ldg(vals + e);

    float4 s = *(const float4*)(sup + (size_t)c * D + lane * 4);
    s.x *= v; s.y *= v; s.z *= v; s.w *= v;
    red_add_v4(out + (size_t)r * D + lane * 4, s);
}

// ---------------------------------------------------------------------------
extern "C" void kernel_launch(void* const* d_in, const int* in_sizes, int n_in,
                              void* d_out, int out_size)
{
    const float* x        = (const float*)d_in[0];
    const float* W        = (const float*)d_in[1];
    const float* lin_bias = (const float*)d_in[2];
    const float* bias     = (const float*)d_in[3];
    const int*   adj_rows = (const int*)d_in[4];
    const int*   adj_cols = (const int*)d_in[5];
    const float* adj_vals = (const float*)d_in[6];
    float* out = (float*)d_out;

    const int M  = in_sizes[0] / D;      // 100000
    const int nE = in_sizes[4];          // 1600000

    float* sup = nullptr;
    cudaGetSymbolAddress((void**)&sup, g_support);

    const int smem = (128 * PADX + TK * D) * sizeof(float);  // ~68 KB
    cudaFuncSetAttribute(gemm_kernel, cudaFuncAttributeMaxDynamicSharedMemorySize, smem);

    gemm_kernel<<<(M + 127) / 128, 256, smem>>>(x, W, lin_bias, sup, M);
    init_kernel<<<1024, 256>>>(out, bias, M);
    spmm_kernel<<<(nE + 7) / 8, 256>>>(sup, adj_rows, adj_cols, adj_vals, out, nE);
}

// round 7
// speedup vs baseline: 1.9441x; 1.0871x over previous
#include <cuda_runtime.h>
#include <cuda_bf16.h>
#include <stdint.h>

// ---------------------------------------------------------------------------
// GraphConv: out = SpMM(adj, x@W + lin_bias) + bias
// ---------------------------------------------------------------------------

#define D 128
#define TK 64
#define PADX 69          // 8*69 % 32 == 8 -> conflict-free A-frag loads

__device__ float g_support[100000 * D];

// packed f32x2 FMA: d = a*b + d   (sm_100+ dual-FP32 pipe, PTX-only)
#define FMA_F32X2(d, a, b) \
    asm("fma.rn.f32x2 %0, %1, %2, %0;" : "+l"(d) : "l"(a), "l"(b))

__device__ __forceinline__ unsigned long long dup_f32x2(float a)
{
    unsigned long long r;
    asm("mov.b64 %0, {%1, %1};" : "=l"(r) : "f"(a));
    return r;
}

// ---------------------------------------------------------------------------
// Kernel 1: support = x @ W + lin_bias   (f32x2 packed-FMA inner loop)
// Block tile 128x128, 256 threads, 8x8 register tile (cols packed in pairs).
// ---------------------------------------------------------------------------
__global__ void __launch_bounds__(256, 2)
gemm_kernel(const float* __restrict__ x, const float* __restrict__ W,
            const float* __restrict__ lin_bias, float* __restrict__ sup, int M)
{
    extern __shared__ float sh[];
    float* xs = sh;                 // [128][PADX]
    float* Ws = sh + 128 * PADX;    // [TK][128]

    const int tid  = threadIdx.x;
    const int warp = tid >> 5;
    const int lane = tid & 31;
    const int lr = lane >> 3;       // 0..3
    const int lc = lane & 7;        // 0..7
    const int wr = warp & 3;        // 0..3
    const int wc = warp >> 2;       // 0..1

    const int rowBase = blockIdx.x * 128;
    const int row0 = wr * 32 + lr * 8;
    const int col0 = wc * 64 + lc * 8;

    unsigned long long acc2[8][4];  // 8 rows x 4 packed col-pairs
#pragma unroll
    for (int r = 0; r < 8; r++)
#pragma unroll
        for (int j = 0; j < 4; j++) acc2[r][j] = 0ull;

    for (int k0 = 0; k0 < D; k0 += TK) {
        for (int i = tid; i < 128 * (TK / 4); i += 256) {
            int m  = i / (TK / 4);
            int kq = (i % (TK / 4)) * 4;
            int gm = rowBase + m;
            float4 v = make_float4(0.f, 0.f, 0.f, 0.f);
            if (gm < M) v = *(const float4*)(x + (size_t)gm * D + k0 + kq);
            float* dst = xs + m * PADX + kq;
            dst[0] = v.x; dst[1] = v.y; dst[2] = v.z; dst[3] = v.w;
        }
        for (int i = tid; i < TK * (D / 4); i += 256) {
            int kk = i / (D / 4);
            int n4 = (i % (D / 4)) * 4;
            *(float4*)(Ws + kk * D + n4) =
                *(const float4*)(W + (size_t)(k0 + kk) * D + n4);
        }
        __syncthreads();

#pragma unroll 4
        for (int k = 0; k < TK; k++) {
            // B fragment: 4x LDS.64 -> packed col pairs (32B-aligned)
            const unsigned long long* wrow =
                (const unsigned long long*)(Ws + k * D + col0);
            unsigned long long bp0 = wrow[0];
            unsigned long long bp1 = wrow[1];
            unsigned long long bp2 = wrow[2];
            unsigned long long bp3 = wrow[3];
#pragma unroll
            for (int r = 0; r < 8; r++) {
                unsigned long long ap = dup_f32x2(xs[(row0 + r) * PADX + k]);
                FMA_F32X2(acc2[r][0], ap, bp0);
                FMA_F32X2(acc2[r][1], ap, bp1);
                FMA_F32X2(acc2[r][2], ap, bp2);
                FMA_F32X2(acc2[r][3], ap, bp3);
            }
        }
        __syncthreads();
    }

    float4 lb0 = *(const float4*)(lin_bias + col0);
    float4 lb1 = *(const float4*)(lin_bias + col0 + 4);
    float lb[8] = {lb0.x, lb0.y, lb0.z, lb0.w, lb1.x, lb1.y, lb1.z, lb1.w};
#pragma unroll
    for (int r = 0; r < 8; r++) {
        int gm = rowBase + row0 + r;
        if (gm < M) {
            float o[8];
#pragma unroll
            for (int j = 0; j < 4; j++) {
                unsigned long long p = acc2[r][j];
                o[2 * j]     = __uint_as_float((unsigned)(p & 0xffffffffu)) + lb[2 * j];
                o[2 * j + 1] = __uint_as_float((unsigned)(p >> 32))         + lb[2 * j + 1];
            }
            float* dst = sup + (size_t)gm * D + col0;
            *(float4*)dst       = make_float4(o[0], o[1], o[2], o[3]);
            *(float4*)(dst + 4) = make_float4(o[4], o[5], o[6], o[7]);
        }
    }
}

// ---------------------------------------------------------------------------
// Kernel 2: out[n][d] = bias[d]
// ---------------------------------------------------------------------------
__global__ void init_kernel(float* __restrict__ out, const float* __restrict__ bias, int M)
{
    int total = M * (D / 4);
    for (int i = blockIdx.x * blockDim.x + threadIdx.x; i < total;
         i += gridDim.x * blockDim.x) {
        int d4 = i & (D / 4 - 1);
        float4 v = *(const float4*)(bias + d4 * 4);
        ((float4*)out)[i] = v;
    }
}

// ---------------------------------------------------------------------------
// Kernel 3: scatter-add, 2 edges per warp (ILP), red.global.add.v4.f32
// ---------------------------------------------------------------------------
__device__ __forceinline__ void red_add_v4(float* addr, float4 v)
{
    asm volatile("red.global.add.v4.f32 [%0], {%1, %2, %3, %4};"
                 :: "l"(addr), "f"(v.x), "f"(v.y), "f"(v.z), "f"(v.w)
                 : "memory");
}

__global__ void __launch_bounds__(256)
spmm_kernel(const float* __restrict__ sup,
            const int* __restrict__ rows, const int* __restrict__ cols,
            const float* __restrict__ vals, float* __restrict__ out, int nE)
{
    int warp = threadIdx.x >> 5;
    int lane = threadIdx.x & 31;
    int e0 = blockIdx.x * 16 + warp * 2;   // 2 edges per warp
    int e1 = e0 + 1;

    if (e0 >= nE) return;
    bool has1 = (e1 < nE);

    int   r0 = __ldg(rows + e0);
    int   c0 = __ldg(cols + e0);
    float v0 = __ldg(vals + e0);
    int   r1 = has1 ? __ldg(rows + e1) : 0;
    int   c1 = has1 ? __ldg(cols + e1) : 0;
    float v1 = has1 ? __ldg(vals + e1) : 0.f;

    // both gathers in flight before either RED
    float4 s0 = *(const float4*)(sup + (size_t)c0 * D + lane * 4);
    float4 s1 = *(const float4*)(sup + (size_t)c1 * D + lane * 4);

    s0.x *= v0; s0.y *= v0; s0.z *= v0; s0.w *= v0;
    red_add_v4(out + (size_t)r0 * D + lane * 4, s0);

    if (has1) {
        s1.x *= v1; s1.y *= v1; s1.z *= v1; s1.w *= v1;
        red_add_v4(out + (size_t)r1 * D + lane * 4, s1);
    }
}

// ---------------------------------------------------------------------------
extern "C" void kernel_launch(void* const* d_in, const int* in_sizes, int n_in,
                              void* d_out, int out_size)
{
    const float* x        = (const float*)d_in[0];
    const float* W        = (const float*)d_in[1];
    const float* lin_bias = (const float*)d_in[2];
    const float* bias     = (const float*)d_in[3];
    const int*   adj_rows = (const int*)d_in[4];
    const int*   adj_cols = (const int*)d_in[5];
    const float* adj_vals = (const float*)d_in[6];
    float* out = (float*)d_out;

    const int M  = in_sizes[0] / D;      // 100000
    const int nE = in_sizes[4];          // 1600000

    float* sup = nullptr;
    cudaGetSymbolAddress((void**)&sup, g_support);

    const int smem = (128 * PADX + TK * D) * sizeof(float);  // ~68 KB
    cudaFuncSetAttribute(gemm_kernel, cudaFuncAttributeMaxDynamicSharedMemorySize, smem);

    gemm_kernel<<<(M + 127) / 128, 256, smem>>>(x, W, lin_bias, sup, M);
    init_kernel<<<1024, 256>>>(out, bias, M);
    spmm_kernel<<<(nE + 15) / 16, 256>>>(sup, adj_rows, adj_cols, adj_vals, out, nE);
}

// round 9
// speedup vs baseline: 2.0316x; 1.0450x over previous
#include <cuda_runtime.h>
#include <cuda_bf16.h>
#include <stdint.h>

// ---------------------------------------------------------------------------
// GraphConv: out = SpMM(adj, x@W + lin_bias) + bias
// GEMM via tensor cores: mma.sync m16n8k8 tf32, 3xTF32 (hi/lo) for fp32 accuracy
// ---------------------------------------------------------------------------

#define D 128
#define TK 32                 // K-chunk per staging round
#define XS_STRIDE 36          // bank(g*36 + t4) = 4g + t4 -> conflict-free
#define WS_STRIDE 136         // bank(t4*136 + g) = 8*t4 + g -> conflict-free

__device__ float g_support[100000 * D];

// split fp32 into tf32 hi + tf32 lo (v ~= hi + lo, |lo| <= 2^-11 |v|)
__device__ __forceinline__ void split_tf32(float v, unsigned& hi, unsigned& lo)
{
    asm("cvt.rna.tf32.f32 %0, %1;" : "=r"(hi) : "f"(v));
    float l = v - __uint_as_float(hi);
    asm("cvt.rna.tf32.f32 %0, %1;" : "=r"(lo) : "f"(l));
}

__device__ __forceinline__ void mma_tf32(float* d, const unsigned* a, const unsigned* b)
{
    asm("mma.sync.aligned.m16n8k8.row.col.f32.tf32.tf32.f32 "
        "{%0,%1,%2,%3}, {%4,%5,%6,%7}, {%8,%9}, {%0,%1,%2,%3};"
        : "+f"(d[0]), "+f"(d[1]), "+f"(d[2]), "+f"(d[3])
        : "r"(a[0]), "r"(a[1]), "r"(a[2]), "r"(a[3]), "r"(b[0]), "r"(b[1]));
}

// ---------------------------------------------------------------------------
// Kernel 1: support = x @ W + lin_bias
// Block 128x128 tile, 256 threads = 8 warps (4 row-warps x 2 col-warps).
// Warp tile 32x64 = 2 m-tiles x 8 n-tiles of m16n8k8.
// ---------------------------------------------------------------------------
__global__ void __launch_bounds__(256, 2)
gemm_kernel(const float* __restrict__ x, const float* __restrict__ W,
            const float* __restrict__ lin_bias, float* __restrict__ sup, int M)
{
    extern __shared__ unsigned sh[];
    unsigned* xs_hi = sh;                        // [128][XS_STRIDE]
    unsigned* xs_lo = xs_hi + 128 * XS_STRIDE;
    unsigned* ws_hi = xs_lo + 128 * XS_STRIDE;   // [TK][WS_STRIDE]
    unsigned* ws_lo = ws_hi + TK * WS_STRIDE;

    const int tid  = threadIdx.x;
    const int warp = tid >> 5;
    const int lane = tid & 31;
    const int g    = lane >> 2;   // 0..7
    const int t4   = lane & 3;    // 0..3

    const int rowBase = blockIdx.x * 128;
    const int warpRow = (warp & 3) * 32;
    const int warpCol = (warp >> 2) * 64;

    float acc[2][8][4];
#pragma unroll
    for (int mt = 0; mt < 2; mt++)
#pragma unroll
        for (int nt = 0; nt < 8; nt++)
#pragma unroll
            for (int i = 0; i < 4; i++) acc[mt][nt][i] = 0.f;

    for (int k0 = 0; k0 < D; k0 += TK) {
        // stage x tile [128 x TK] as tf32 hi/lo
        for (int i = tid; i < 128 * (TK / 4); i += 256) {
            int m  = i / (TK / 4);
            int kq = (i % (TK / 4)) * 4;
            int gm = rowBase + m;
            float4 v = make_float4(0.f, 0.f, 0.f, 0.f);
            if (gm < M) v = *(const float4*)(x + (size_t)gm * D + k0 + kq);
            unsigned* dh = xs_hi + m * XS_STRIDE + kq;
            unsigned* dl = xs_lo + m * XS_STRIDE + kq;
            split_tf32(v.x, dh[0], dl[0]);
            split_tf32(v.y, dh[1], dl[1]);
            split_tf32(v.z, dh[2], dl[2]);
            split_tf32(v.w, dh[3], dl[3]);
        }
        // stage W chunk [TK x 128] as tf32 hi/lo
        for (int i = tid; i < TK * (D / 4); i += 256) {
            int kk = i / (D / 4);
            int n4 = (i % (D / 4)) * 4;
            float4 v = *(const float4*)(W + (size_t)(k0 + kk) * D + n4);
            unsigned* dh = ws_hi + kk * WS_STRIDE + n4;
            unsigned* dl = ws_lo + kk * WS_STRIDE + n4;
            split_tf32(v.x, dh[0], dl[0]);
            split_tf32(v.y, dh[1], dl[1]);
            split_tf32(v.z, dh[2], dl[2]);
            split_tf32(v.w, dh[3], dl[3]);
        }
        __syncthreads();

#pragma unroll
        for (int ks = 0; ks < TK; ks += 8) {
            // B fragments for all 8 n-tiles (hi & lo)
            unsigned bh[8][2], bl[8][2];
#pragma unroll
            for (int nt = 0; nt < 8; nt++) {
                int col = warpCol + nt * 8 + g;
                int kA = ks + t4;
                bh[nt][0] = ws_hi[kA * WS_STRIDE + col];
                bh[nt][1] = ws_hi[(kA + 4) * WS_STRIDE + col];
                bl[nt][0] = ws_lo[kA * WS_STRIDE + col];
                bl[nt][1] = ws_lo[(kA + 4) * WS_STRIDE + col];
            }
#pragma unroll
            for (int mt = 0; mt < 2; mt++) {
                int r0 = warpRow + mt * 16 + g;
                unsigned ah[4], al[4];
                ah[0] = xs_hi[r0 * XS_STRIDE + ks + t4];
                ah[1] = xs_hi[(r0 + 8) * XS_STRIDE + ks + t4];
                ah[2] = xs_hi[r0 * XS_STRIDE + ks + t4 + 4];
                ah[3] = xs_hi[(r0 + 8) * XS_STRIDE + ks + t4 + 4];
                al[0] = xs_lo[r0 * XS_STRIDE + ks + t4];
                al[1] = xs_lo[(r0 + 8) * XS_STRIDE + ks + t4];
                al[2] = xs_lo[r0 * XS_STRIDE + ks + t4 + 4];
                al[3] = xs_lo[(r0 + 8) * XS_STRIDE + ks + t4 + 4];
#pragma unroll
                for (int nt = 0; nt < 8; nt++) {
                    mma_tf32(acc[mt][nt], ah, bh[nt]);   // hi*hi
                    mma_tf32(acc[mt][nt], ah, bl[nt]);   // hi*lo
                    mma_tf32(acc[mt][nt], al, bh[nt]);   // lo*hi
                }
            }
        }
        __syncthreads();
    }

    // epilogue: + lin_bias, store (float2 per m16n8 D-fragment row-pair)
#pragma unroll
    for (int nt = 0; nt < 8; nt++) {
        int n = warpCol + nt * 8 + t4 * 2;
        float lb0 = lin_bias[n];
        float lb1 = lin_bias[n + 1];
#pragma unroll
        for (int mt = 0; mt < 2; mt++) {
            int gm0 = rowBase + warpRow + mt * 16 + g;
            int gm1 = gm0 + 8;
            if (gm0 < M)
                *(float2*)(sup + (size_t)gm0 * D + n) =
                    make_float2(acc[mt][nt][0] + lb0, acc[mt][nt][1] + lb1);
            if (gm1 < M)
                *(float2*)(sup + (size_t)gm1 * D + n) =
                    make_float2(acc[mt][nt][2] + lb0, acc[mt][nt][3] + lb1);
        }
    }
}

// ---------------------------------------------------------------------------
// Kernel 2: out[n][d] = bias[d]
// ---------------------------------------------------------------------------
__global__ void init_kernel(float* __restrict__ out, const float* __restrict__ bias, int M)
{
    int total = M * (D / 4);
    for (int i = blockIdx.x * blockDim.x + threadIdx.x; i < total;
         i += gridDim.x * blockDim.x) {
        int d4 = i & (D / 4 - 1);
        float4 v = *(const float4*)(bias + d4 * 4);
        ((float4*)out)[i] = v;
    }
}

// ---------------------------------------------------------------------------
// Kernel 3: scatter-add, 2 edges per warp, red.global.add.v4.f32
// ---------------------------------------------------------------------------
__device__ __forceinline__ void red_add_v4(float* addr, float4 v)
{
    asm volatile("red.global.add.v4.f32 [%0], {%1, %2, %3, %4};"
                 :: "l"(addr), "f"(v.x), "f"(v.y), "f"(v.z), "f"(v.w)
                 : "memory");
}

__global__ void __launch_bounds__(256)
spmm_kernel(const float* __restrict__ sup,
            const int* __restrict__ rows, const int* __restrict__ cols,
            const float* __restrict__ vals, float* __restrict__ out, int nE)
{
    int warp = threadIdx.x >> 5;
    int lane = threadIdx.x & 31;
    int e0 = blockIdx.x * 16 + warp * 2;
    int e1 = e0 + 1;

    if (e0 >= nE) return;
    bool has1 = (e1 < nE);

    int   r0 = __ldg(rows + e0);
    int   c0 = __ldg(cols + e0);
    float v0 = __ldg(vals + e0);
    int   r1 = has1 ? __ldg(rows + e1) : 0;
    int   c1 = has1 ? __ldg(cols + e1) : 0;
    float v1 = has1 ? __ldg(vals + e1) : 0.f;

    float4 s0 = *(const float4*)(sup + (size_t)c0 * D + lane * 4);
    float4 s1 = *(const float4*)(sup + (size_t)c1 * D + lane * 4);

    s0.x *= v0; s0.y *= v0; s0.z *= v0; s0.w *= v0;
    red_add_v4(out + (size_t)r0 * D + lane * 4, s0);

    if (has1) {
        s1.x *= v1; s1.y *= v1; s1.z *= v1; s1.w *= v1;
        red_add_v4(out + (size_t)r1 * D + lane * 4, s1);
    }
}

// ---------------------------------------------------------------------------
extern "C" void kernel_launch(void* const* d_in, const int* in_sizes, int n_in,
                              void* d_out, int out_size)
{
    const float* x        = (const float*)d_in[0];
    const float* W        = (const float*)d_in[1];
    const float* lin_bias = (const float*)d_in[2];
    const float* bias     = (const float*)d_in[3];
    const int*   adj_rows = (const int*)d_in[4];
    const int*   adj_cols = (const int*)d_in[5];
    const float* adj_vals = (const float*)d_in[6];
    float* out = (float*)d_out;

    const int M  = in_sizes[0] / D;      // 100000
    const int nE = in_sizes[4];          // 1600000

    float* sup = nullptr;
    cudaGetSymbolAddress((void**)&sup, g_support);

    const int smem = (2 * 128 * XS_STRIDE + 2 * TK * WS_STRIDE) * sizeof(unsigned); // ~70.7 KB
    cudaFuncSetAttribute(gemm_kernel, cudaFuncAttributeMaxDynamicSharedMemorySize, smem);

    gemm_kernel<<<(M + 127) / 128, 256, smem>>>(x, W, lin_bias, sup, M);
    init_kernel<<<1024, 256>>>(out, bias, M);
    spmm_kernel<<<(nE + 15) / 16, 256>>>(sup, adj_rows, adj_cols, adj_vals, out, nE);
}

// round 11
// speedup vs baseline: 2.3061x; 1.1351x over previous
#include <cuda_runtime.h>
#include <cuda_fp16.h>
#include <cuda_bf16.h>
#include <stdint.h>

// ---------------------------------------------------------------------------
// GraphConv: out = SpMM(adj, x@W + lin_bias) + bias
// GEMM: mma.sync m16n8k16 bf16, 3-term hi/lo split (~1.5e-5 rel accuracy)
// support stored fp16 (halves SpMM gather bytes)
// ---------------------------------------------------------------------------

#define D 128
#define TK 32
#define XS32 20     // b32 row stride of x tile (16 k-pairs + 4 pad); 20 = 4*5
#define WS32 132    // b32 row stride of W k-pair rows (128 cols + 4 pad); 132 = 4*33

__device__ __half g_support[100000 * D];   // 25.6 MB fp16 scratch

// split fp32 -> bf16 hi + bf16 lo, pack two adjacent elements per plane
__device__ __forceinline__ void split2_bf16(float a, float b, unsigned& hi, unsigned& lo)
{
    __nv_bfloat16 ah = __float2bfloat16_rn(a);
    __nv_bfloat16 bh = __float2bfloat16_rn(b);
    __nv_bfloat16 al = __float2bfloat16_rn(a - __bfloat162float(ah));
    __nv_bfloat16 bl = __float2bfloat16_rn(b - __bfloat162float(bh));
    __nv_bfloat162 H = __halves2bfloat162(ah, bh);   // .x = low 16 bits
    __nv_bfloat162 L = __halves2bfloat162(al, bl);
    hi = *(unsigned*)&H;
    lo = *(unsigned*)&L;
}

__device__ __forceinline__ void mma_bf16(float* d, const unsigned* a, const unsigned* b)
{
    asm("mma.sync.aligned.m16n8k16.row.col.f32.bf16.bf16.f32 "
        "{%0,%1,%2,%3}, {%4,%5,%6,%7}, {%8,%9}, {%0,%1,%2,%3};"
        : "+f"(d[0]), "+f"(d[1]), "+f"(d[2]), "+f"(d[3])
        : "r"(a[0]), "r"(a[1]), "r"(a[2]), "r"(a[3]), "r"(b[0]), "r"(b[1]));
}

// ---------------------------------------------------------------------------
// Kernel 1: support(fp16) = x @ W + lin_bias
// Block 128x128, 256 threads = 8 warps (4 row x 2 col). Warp tile 32x64.
// smem: xs[128][XS32] u32 (packed bf16x2 k-pairs) x2 planes,
//       ws[16][WS32]  u32 (k-pair-major, packed)   x2 planes.  ~37.4 KB
// ---------------------------------------------------------------------------
__global__ void __launch_bounds__(256, 2)
gemm_kernel(const float* __restrict__ x, const float* __restrict__ W,
            const float* __restrict__ lin_bias, __half* __restrict__ sup, int M)
{
    extern __shared__ unsigned sh[];
    unsigned* xs_hi = sh;                          // [128][XS32]
    unsigned* xs_lo = xs_hi + 128 * XS32;
    unsigned* ws_hi = xs_lo + 128 * XS32;          // [TK/2][WS32]
    unsigned* ws_lo = ws_hi + (TK / 2) * WS32;

    const int tid  = threadIdx.x;
    const int warp = tid >> 5;
    const int lane = tid & 31;
    const int g    = lane >> 2;   // 0..7
    const int t4   = lane & 3;    // 0..3

    const int rowBase = blockIdx.x * 128;
    const int warpRow = (warp & 3) * 32;
    const int warpCol = (warp >> 2) * 64;

    float acc[2][8][4];
#pragma unroll
    for (int mt = 0; mt < 2; mt++)
#pragma unroll
        for (int nt = 0; nt < 8; nt++)
#pragma unroll
            for (int i = 0; i < 4; i++) acc[mt][nt][i] = 0.f;

    for (int k0 = 0; k0 < D; k0 += TK) {
        // stage x tile [128 x TK]: packed k-pairs, uint2 stores (conflict-free phases)
        for (int i = tid; i < 128 * (TK / 4); i += 256) {
            int m  = i >> 3;
            int kq = (i & 7) * 4;
            int gm = rowBase + m;
            float4 v = make_float4(0.f, 0.f, 0.f, 0.f);
            if (gm < M) v = *(const float4*)(x + (size_t)gm * D + k0 + kq);
            unsigned h0, l0, h1, l1;
            split2_bf16(v.x, v.y, h0, l0);
            split2_bf16(v.z, v.w, h1, l1);
            uint2 ph = make_uint2(h0, h1);
            uint2 pl = make_uint2(l0, l1);
            *(uint2*)(xs_hi + m * XS32 + (kq >> 1)) = ph;
            *(uint2*)(xs_lo + m * XS32 + (kq >> 1)) = pl;
        }
        // stage W chunk [TK x 128] k-pair-major: uint4 stores (conflict-free)
        for (int i = tid; i < (TK / 2) * (D / 4); i += 256) {
            int k2 = i >> 5;
            int n4 = (i & 31) * 4;
            float4 va = *(const float4*)(W + (size_t)(k0 + 2 * k2)     * D + n4);
            float4 vb = *(const float4*)(W + (size_t)(k0 + 2 * k2 + 1) * D + n4);
            uint4 ph, pl;
            split2_bf16(va.x, vb.x, ph.x, pl.x);
            split2_bf16(va.y, vb.y, ph.y, pl.y);
            split2_bf16(va.z, vb.z, ph.z, pl.z);
            split2_bf16(va.w, vb.w, ph.w, pl.w);
            *(uint4*)(ws_hi + k2 * WS32 + n4) = ph;
            *(uint4*)(ws_lo + k2 * WS32 + n4) = pl;
        }
        __syncthreads();

#pragma unroll
        for (int ks2 = 0; ks2 < TK / 2; ks2 += 8) {   // two k16 steps per chunk
            unsigned bh[8][2], bl[8][2];
#pragma unroll
            for (int nt = 0; nt < 8; nt++) {
                int col = warpCol + nt * 8 + g;
                bh[nt][0] = ws_hi[(ks2 + t4)     * WS32 + col];
                bh[nt][1] = ws_hi[(ks2 + t4 + 4) * WS32 + col];
                bl[nt][0] = ws_lo[(ks2 + t4)     * WS32 + col];
                bl[nt][1] = ws_lo[(ks2 + t4 + 4) * WS32 + col];
            }
#pragma unroll
            for (int mt = 0; mt < 2; mt++) {
                int r0 = warpRow + mt * 16 + g;
                unsigned ah[4], al[4];
                ah[0] = xs_hi[r0       * XS32 + ks2 + t4];
                ah[1] = xs_hi[(r0 + 8) * XS32 + ks2 + t4];
                ah[2] = xs_hi[r0       * XS32 + ks2 + t4 + 4];
                ah[3] = xs_hi[(r0 + 8) * XS32 + ks2 + t4 + 4];
                al[0] = xs_lo[r0       * XS32 + ks2 + t4];
                al[1] = xs_lo[(r0 + 8) * XS32 + ks2 + t4];
                al[2] = xs_lo[r0       * XS32 + ks2 + t4 + 4];
                al[3] = xs_lo[(r0 + 8) * XS32 + ks2 + t4 + 4];
#pragma unroll
                for (int nt = 0; nt < 8; nt++) {
                    mma_bf16(acc[mt][nt], ah, bh[nt]);   // hi*hi
                    mma_bf16(acc[mt][nt], ah, bl[nt]);   // hi*lo
                    mma_bf16(acc[mt][nt], al, bh[nt]);   // lo*hi
                }
            }
        }
        __syncthreads();
    }

    // epilogue: + lin_bias, convert to fp16, half2 stores
#pragma unroll
    for (int nt = 0; nt < 8; nt++) {
        int n = warpCol + nt * 8 + t4 * 2;
        float lb0 = lin_bias[n];
        float lb1 = lin_bias[n + 1];
#pragma unroll
        for (int mt = 0; mt < 2; mt++) {
            int gm0 = rowBase + warpRow + mt * 16 + g;
            int gm1 = gm0 + 8;
            if (gm0 < M)
                *(__half2*)(sup + (size_t)gm0 * D + n) =
                    __floats2half2_rn(acc[mt][nt][0] + lb0, acc[mt][nt][1] + lb1);
            if (gm1 < M)
                *(__half2*)(sup + (size_t)gm1 * D + n) =
                    __floats2half2_rn(acc[mt][nt][2] + lb0, acc[mt][nt][3] + lb1);
        }
    }
}

// ---------------------------------------------------------------------------
// Kernel 2: out[n][d] = bias[d]
// ---------------------------------------------------------------------------
__global__ void init_kernel(float* __restrict__ out, const float* __restrict__ bias, int M)
{
    int total = M * (D / 4);
    for (int i = blockIdx.x * blockDim.x + threadIdx.x; i < total;
         i += gridDim.x * blockDim.x) {
        int d4 = i & (D / 4 - 1);
        float4 v = *(const float4*)(bias + d4 * 4);
        ((float4*)out)[i] = v;
    }
}

// ---------------------------------------------------------------------------
// Kernel 3: scatter-add. fp16 gather (8B/lane), fp32 red.global.add.v4.
// 2 edges per warp for ILP.
// ---------------------------------------------------------------------------
__device__ __forceinline__ void red_add_v4(float* addr, float4 v)
{
    asm volatile("red.global.add.v4.f32 [%0], {%1, %2, %3, %4};"
                 :: "l"(addr), "f"(v.x), "f"(v.y), "f"(v.z), "f"(v.w)
                 : "memory");
}

__global__ void __launch_bounds__(256)
spmm_kernel(const __half* __restrict__ sup,
            const int* __restrict__ rows, const int* __restrict__ cols,
            const float* __restrict__ vals, float* __restrict__ out, int nE)
{
    int warp = threadIdx.x >> 5;
    int lane = threadIdx.x & 31;
    int e0 = blockIdx.x * 16 + warp * 2;
    int e1 = e0 + 1;

    if (e0 >= nE) return;
    bool has1 = (e1 < nE);

    int   r0 = __ldg(rows + e0);
    int   c0 = __ldg(cols + e0);
    float v0 = __ldg(vals + e0);
    int   r1 = has1 ? __ldg(rows + e1) : 0;
    int   c1 = has1 ? __ldg(cols + e1) : 0;
    float v1 = has1 ? __ldg(vals + e1) : 0.f;

    // both 8B gathers in flight before either RED
    uint2 q0 = *(const uint2*)(sup + (size_t)c0 * D + lane * 4);
    uint2 q1 = *(const uint2*)(sup + (size_t)c1 * D + lane * 4);

    float2 f00 = __half22float2(*(__half2*)&q0.x);
    float2 f01 = __half22float2(*(__half2*)&q0.y);
    red_add_v4(out + (size_t)r0 * D + lane * 4,
               make_float4(f00.x * v0, f00.y * v0, f01.x * v0, f01.y * v0));

    if (has1) {
        float2 f10 = __half22float2(*(__half2*)&q1.x);
        float2 f11 = __half22float2(*(__half2*)&q1.y);
        red_add_v4(out + (size_t)r1 * D + lane * 4,
                   make_float4(f10.x * v1, f10.y * v1, f11.x * v1, f11.y * v1));
    }
}

// ---------------------------------------------------------------------------
extern "C" void kernel_launch(void* const* d_in, const int* in_sizes, int n_in,
                              void* d_out, int out_size)
{
    const float* x        = (const float*)d_in[0];
    const float* W        = (const float*)d_in[1];
    const float* lin_bias = (const float*)d_in[2];
    const float* bias     = (const float*)d_in[3];
    const int*   adj_rows = (const int*)d_in[4];
    const int*   adj_cols = (const int*)d_in[5];
    const float* adj_vals = (const float*)d_in[6];
    float* out = (float*)d_out;

    const int M  = in_sizes[0] / D;      // 100000
    const int nE = in_sizes[4];          // 1600000

    __half* sup = nullptr;
    cudaGetSymbolAddress((void**)&sup, g_support);

    const int smem = (2 * 128 * XS32 + 2 * (TK / 2) * WS32) * sizeof(unsigned); // ~37.4 KB
    cudaFuncSetAttribute(gemm_kernel, cudaFuncAttributeMaxDynamicSharedMemorySize, smem);

    gemm_kernel<<<(M + 127) / 128, 256, smem>>>(x, W, lin_bias, sup, M);
    init_kernel<<<1024, 256>>>(out, bias, M);
    spmm_kernel<<<(nE + 15) / 16, 256>>>(sup, adj_rows, adj_cols, adj_vals, out, nE);
}

// round 12
// speedup vs baseline: 3.3899x; 1.4700x over previous
#include <cuda_runtime.h>
#include <cuda_fp16.h>
#include <cuda_bf16.h>
#include <stdint.h>

// ---------------------------------------------------------------------------
// GraphConv: out = SpMM(adj, x@W + lin_bias) + bias
// GEMM: mma m16n8k16 bf16 3-term hi/lo split; support stored fp16.
// SpMM: build CSR on the fly (hist + scan + scatter), then warp-per-row
//       gather-accumulate -> ONE store per row. No RED/atomic output traffic.
// ---------------------------------------------------------------------------

#define D 128
#define TK 32
#define XS32 20
#define WS32 132
#define NMAX 100000
#define EMAX 1600000

__device__ __half g_support[NMAX * D];       // 25.6 MB
__device__ int    g_rowptr[NMAX + 1];
__device__ int    g_cursor[NMAX];
__device__ int    g_bsums[128];
__device__ uint2  g_edges[EMAX];             // packed (col, val_bits), 12.8 MB

// ---------------------------------------------------------------------------
// GEMM (unchanged from R11 best)
// ---------------------------------------------------------------------------
__device__ __forceinline__ void split2_bf16(float a, float b, unsigned& hi, unsigned& lo)
{
    __nv_bfloat16 ah = __float2bfloat16_rn(a);
    __nv_bfloat16 bh = __float2bfloat16_rn(b);
    __nv_bfloat16 al = __float2bfloat16_rn(a - __bfloat162float(ah));
    __nv_bfloat16 bl = __float2bfloat16_rn(b - __bfloat162float(bh));
    __nv_bfloat162 H = __halves2bfloat162(ah, bh);
    __nv_bfloat162 L = __halves2bfloat162(al, bl);
    hi = *(unsigned*)&H;
    lo = *(unsigned*)&L;
}

__device__ __forceinline__ void mma_bf16(float* d, const unsigned* a, const unsigned* b)
{
    asm("mma.sync.aligned.m16n8k16.row.col.f32.bf16.bf16.f32 "
        "{%0,%1,%2,%3}, {%4,%5,%6,%7}, {%8,%9}, {%0,%1,%2,%3};"
        : "+f"(d[0]), "+f"(d[1]), "+f"(d[2]), "+f"(d[3])
        : "r"(a[0]), "r"(a[1]), "r"(a[2]), "r"(a[3]), "r"(b[0]), "r"(b[1]));
}

__global__ void __launch_bounds__(256, 2)
gemm_kernel(const float* __restrict__ x, const float* __restrict__ W,
            const float* __restrict__ lin_bias, __half* __restrict__ sup, int M)
{
    extern __shared__ unsigned sh[];
    unsigned* xs_hi = sh;
    unsigned* xs_lo = xs_hi + 128 * XS32;
    unsigned* ws_hi = xs_lo + 128 * XS32;
    unsigned* ws_lo = ws_hi + (TK / 2) * WS32;

    const int tid  = threadIdx.x;
    const int warp = tid >> 5;
    const int lane = tid & 31;
    const int g    = lane >> 2;
    const int t4   = lane & 3;

    const int rowBase = blockIdx.x * 128;
    const int warpRow = (warp & 3) * 32;
    const int warpCol = (warp >> 2) * 64;

    float acc[2][8][4];
#pragma unroll
    for (int mt = 0; mt < 2; mt++)
#pragma unroll
        for (int nt = 0; nt < 8; nt++)
#pragma unroll
            for (int i = 0; i < 4; i++) acc[mt][nt][i] = 0.f;

    for (int k0 = 0; k0 < D; k0 += TK) {
        for (int i = tid; i < 128 * (TK / 4); i += 256) {
            int m  = i >> 3;
            int kq = (i & 7) * 4;
            int gm = rowBase + m;
            float4 v = make_float4(0.f, 0.f, 0.f, 0.f);
            if (gm < M) v = *(const float4*)(x + (size_t)gm * D + k0 + kq);
            unsigned h0, l0, h1, l1;
            split2_bf16(v.x, v.y, h0, l0);
            split2_bf16(v.z, v.w, h1, l1);
            *(uint2*)(xs_hi + m * XS32 + (kq >> 1)) = make_uint2(h0, h1);
            *(uint2*)(xs_lo + m * XS32 + (kq >> 1)) = make_uint2(l0, l1);
        }
        for (int i = tid; i < (TK / 2) * (D / 4); i += 256) {
            int k2 = i >> 5;
            int n4 = (i & 31) * 4;
            float4 va = *(const float4*)(W + (size_t)(k0 + 2 * k2)     * D + n4);
            float4 vb = *(const float4*)(W + (size_t)(k0 + 2 * k2 + 1) * D + n4);
            uint4 ph, pl;
            split2_bf16(va.x, vb.x, ph.x, pl.x);
            split2_bf16(va.y, vb.y, ph.y, pl.y);
            split2_bf16(va.z, vb.z, ph.z, pl.z);
            split2_bf16(va.w, vb.w, ph.w, pl.w);
            *(uint4*)(ws_hi + k2 * WS32 + n4) = ph;
            *(uint4*)(ws_lo + k2 * WS32 + n4) = pl;
        }
        __syncthreads();

#pragma unroll
        for (int ks2 = 0; ks2 < TK / 2; ks2 += 8) {
            unsigned bh[8][2], bl[8][2];
#pragma unroll
            for (int nt = 0; nt < 8; nt++) {
                int col = warpCol + nt * 8 + g;
                bh[nt][0] = ws_hi[(ks2 + t4)     * WS32 + col];
                bh[nt][1] = ws_hi[(ks2 + t4 + 4) * WS32 + col];
                bl[nt][0] = ws_lo[(ks2 + t4)     * WS32 + col];
                bl[nt][1] = ws_lo[(ks2 + t4 + 4) * WS32 + col];
            }
#pragma unroll
            for (int mt = 0; mt < 2; mt++) {
                int r0 = warpRow + mt * 16 + g;
                unsigned ah[4], al[4];
                ah[0] = xs_hi[r0       * XS32 + ks2 + t4];
                ah[1] = xs_hi[(r0 + 8) * XS32 + ks2 + t4];
                ah[2] = xs_hi[r0       * XS32 + ks2 + t4 + 4];
                ah[3] = xs_hi[(r0 + 8) * XS32 + ks2 + t4 + 4];
                al[0] = xs_lo[r0       * XS32 + ks2 + t4];
                al[1] = xs_lo[(r0 + 8) * XS32 + ks2 + t4];
                al[2] = xs_lo[r0       * XS32 + ks2 + t4 + 4];
                al[3] = xs_lo[(r0 + 8) * XS32 + ks2 + t4 + 4];
#pragma unroll
                for (int nt = 0; nt < 8; nt++) {
                    mma_bf16(acc[mt][nt], ah, bh[nt]);
                    mma_bf16(acc[mt][nt], ah, bl[nt]);
                    mma_bf16(acc[mt][nt], al, bh[nt]);
                }
            }
        }
        __syncthreads();
    }

#pragma unroll
    for (int nt = 0; nt < 8; nt++) {
        int n = warpCol + nt * 8 + t4 * 2;
        float lb0 = lin_bias[n];
        float lb1 = lin_bias[n + 1];
#pragma unroll
        for (int mt = 0; mt < 2; mt++) {
            int gm0 = rowBase + warpRow + mt * 16 + g;
            int gm1 = gm0 + 8;
            if (gm0 < M)
                *(__half2*)(sup + (size_t)gm0 * D + n) =
                    __floats2half2_rn(acc[mt][nt][0] + lb0, acc[mt][nt][1] + lb1);
            if (gm1 < M)
                *(__half2*)(sup + (size_t)gm1 * D + n) =
                    __floats2half2_rn(acc[mt][nt][2] + lb0, acc[mt][nt][3] + lb1);
        }
    }
}

// ---------------------------------------------------------------------------
// CSR build: histogram -> 2-level exclusive scan -> scatter
// ---------------------------------------------------------------------------
__global__ void hist_kernel(const int* __restrict__ rows, int* __restrict__ cnt, int nE)
{
    for (int e = blockIdx.x * blockDim.x + threadIdx.x; e < nE;
         e += gridDim.x * blockDim.x)
        atomicAdd(cnt + __ldg(rows + e), 1);
}

// block-level exclusive scan of 1024 elements; write block total
__global__ void scan1_kernel(int* __restrict__ data, int* __restrict__ bsums, int N)
{
    __shared__ int s[1024];
    int i = blockIdx.x * 1024 + threadIdx.x;
    int v = (i < N) ? data[i] : 0;
    s[threadIdx.x] = v;
    __syncthreads();
#pragma unroll
    for (int off = 1; off < 1024; off <<= 1) {
        int t = (threadIdx.x >= off) ? s[threadIdx.x - off] : 0;
        __syncthreads();
        s[threadIdx.x] += t;
        __syncthreads();
    }
    if (i < N) data[i] = s[threadIdx.x] - v;     // exclusive
    if (threadIdx.x == 1023) bsums[blockIdx.x] = s[1023];
}

// single-block exclusive scan of block sums (NB <= 128)
__global__ void scan2_kernel(int* __restrict__ bsums, int NB)
{
    __shared__ int s[128];
    int v = (threadIdx.x < NB) ? bsums[threadIdx.x] : 0;
    s[threadIdx.x] = v;
    __syncthreads();
#pragma unroll
    for (int off = 1; off < 128; off <<= 1) {
        int t = (threadIdx.x >= off) ? s[threadIdx.x - off] : 0;
        __syncthreads();
        s[threadIdx.x] += t;
        __syncthreads();
    }
    if (threadIdx.x < NB) bsums[threadIdx.x] = s[threadIdx.x] - v;
}

// add block offsets; mirror into cursor; set rowptr[N]=nE
__global__ void scan3_kernel(int* __restrict__ rowptr, int* __restrict__ cursor,
                             const int* __restrict__ bsums, int N, int nE)
{
    int i = blockIdx.x * 1024 + threadIdx.x;
    if (i < N) {
        int v = rowptr[i] + bsums[blockIdx.x];
        rowptr[i] = v;
        cursor[i] = v;
    }
    if (i == 0) rowptr[N] = nE;
}

__global__ void scatter_kernel(const int* __restrict__ rows, const int* __restrict__ cols,
                               const float* __restrict__ vals, int* __restrict__ cursor,
                               uint2* __restrict__ edges, int nE)
{
    for (int e = blockIdx.x * blockDim.x + threadIdx.x; e < nE;
         e += gridDim.x * blockDim.x) {
        int r = __ldg(rows + e);
        int p = atomicAdd(cursor + r, 1);
        edges[p] = make_uint2((unsigned)__ldg(cols + e),
                              __float_as_uint(__ldg(vals + e)));
    }
}

// ---------------------------------------------------------------------------
// CSR SpMM: warp per row. acc starts at bias; gather fp16 support rows;
// one float4 store per lane at the end. Zero atomic traffic.
// ---------------------------------------------------------------------------
__global__ void __launch_bounds__(256)
csr_kernel(const __half* __restrict__ sup, const uint2* __restrict__ edges,
           const int* __restrict__ rowptr, const float* __restrict__ bias,
           float* __restrict__ out, int N)
{
    int r = blockIdx.x * 8 + (threadIdx.x >> 5);
    if (r >= N) return;
    int lane = threadIdx.x & 31;

    int s = __ldg(rowptr + r);
    int e = __ldg(rowptr + r + 1);

    float4 acc = *(const float4*)(bias + lane * 4);

    int i = s;
    for (; i + 1 < e; i += 2) {
        uint2 ev0 = __ldg(edges + i);
        uint2 ev1 = __ldg(edges + i + 1);
        uint2 q0 = *(const uint2*)(sup + (size_t)ev0.x * D + lane * 4);
        uint2 q1 = *(const uint2*)(sup + (size_t)ev1.x * D + lane * 4);
        float v0 = __uint_as_float(ev0.y);
        float v1 = __uint_as_float(ev1.y);
        float2 a0 = __half22float2(*(__half2*)&q0.x);
        float2 b0 = __half22float2(*(__half2*)&q0.y);
        acc.x = fmaf(a0.x, v0, acc.x); acc.y = fmaf(a0.y, v0, acc.y);
        acc.z = fmaf(b0.x, v0, acc.z); acc.w = fmaf(b0.y, v0, acc.w);
        float2 a1 = __half22float2(*(__half2*)&q1.x);
        float2 b1 = __half22float2(*(__half2*)&q1.y);
        acc.x = fmaf(a1.x, v1, acc.x); acc.y = fmaf(a1.y, v1, acc.y);
        acc.z = fmaf(b1.x, v1, acc.z); acc.w = fmaf(b1.y, v1, acc.w);
    }
    if (i < e) {
        uint2 ev = __ldg(edges + i);
        uint2 q = *(const uint2*)(sup + (size_t)ev.x * D + lane * 4);
        float v = __uint_as_float(ev.y);
        float2 a = __half22float2(*(__half2*)&q.x);
        float2 b = __half22float2(*(__half2*)&q.y);
        acc.x = fmaf(a.x, v, acc.x); acc.y = fmaf(a.y, v, acc.y);
        acc.z = fmaf(b.x, v, acc.z); acc.w = fmaf(b.y, v, acc.w);
    }

    *(float4*)(out + (size_t)r * D + lane * 4) = acc;
}

// ---------------------------------------------------------------------------
extern "C" void kernel_launch(void* const* d_in, const int* in_sizes, int n_in,
                              void* d_out, int out_size)
{
    const float* x        = (const float*)d_in[0];
    const float* W        = (const float*)d_in[1];
    const float* lin_bias = (const float*)d_in[2];
    const float* bias     = (const float*)d_in[3];
    const int*   adj_rows = (const int*)d_in[4];
    const int*   adj_cols = (const int*)d_in[5];
    const float* adj_vals = (const float*)d_in[6];
    float* out = (float*)d_out;

    const int M  = in_sizes[0] / D;      // 100000
    const int nE = in_sizes[4];          // 1600000

    __half* sup = nullptr;   cudaGetSymbolAddress((void**)&sup, g_support);
    int* rowptr = nullptr;   cudaGetSymbolAddress((void**)&rowptr, g_rowptr);
    int* cursor = nullptr;   cudaGetSymbolAddress((void**)&cursor, g_cursor);
    int* bsums  = nullptr;   cudaGetSymbolAddress((void**)&bsums, g_bsums);
    uint2* edges = nullptr;  cudaGetSymbolAddress((void**)&edges, g_edges);

    const int smem = (2 * 128 * XS32 + 2 * (TK / 2) * WS32) * sizeof(unsigned);
    cudaFuncSetAttribute(gemm_kernel, cudaFuncAttributeMaxDynamicSharedMemorySize, smem);

    const int NB = (M + 1023) / 1024;    // 98 scan blocks

    // CSR build (independent of GEMM)
    cudaMemsetAsync(rowptr, 0, (M + 1) * sizeof(int));
    hist_kernel<<<256, 256>>>(adj_rows, rowptr, nE);

    // GEMM can proceed between (stream-serialized anyway)
    gemm_kernel<<<(M + 127) / 128, 256, smem>>>(x, W, lin_bias, sup, M);

    scan1_kernel<<<NB, 1024>>>(rowptr, bsums, M);
    scan2_kernel<<<1, 128>>>(bsums, NB);
    scan3_kernel<<<NB, 1024>>>(rowptr, cursor, bsums, M, nE);
    scatter_kernel<<<256, 256>>>(adj_rows, adj_cols, adj_vals, cursor, edges, nE);

    csr_kernel<<<(M + 7) / 8, 256>>>(sup, edges, rowptr, bias, out, M);
}

// round 13
// speedup vs baseline: 3.7680x; 1.1115x over previous
#include <cuda_runtime.h>
#include <cuda_fp16.h>
#include <cuda_bf16.h>
#include <stdint.h>

// ---------------------------------------------------------------------------
// GraphConv: out = SpMM(adj, x@W + lin_bias) + bias
// GEMM: mma m16n8k16 bf16 3-term hi/lo; W staged once; x register-prefetch.
// SpMM: CSR build (hist + scan + scatter) then warp-per-row gather, 4-edge ILP.
// ---------------------------------------------------------------------------

#define D 128
#define TK 32
#define XS32 20
#define WS32 132
#define NMAX 100000
#define EMAX 1600000

__device__ __half g_support[NMAX * D];
__device__ int    g_rowptr[NMAX + 1];
__device__ int    g_cursor[NMAX];
__device__ int    g_bsums[128];
__device__ uint2  g_edges[EMAX];

// ---------------------------------------------------------------------------
__device__ __forceinline__ void split2_bf16(float a, float b, unsigned& hi, unsigned& lo)
{
    __nv_bfloat16 ah = __float2bfloat16_rn(a);
    __nv_bfloat16 bh = __float2bfloat16_rn(b);
    __nv_bfloat16 al = __float2bfloat16_rn(a - __bfloat162float(ah));
    __nv_bfloat16 bl = __float2bfloat16_rn(b - __bfloat162float(bh));
    __nv_bfloat162 H = __halves2bfloat162(ah, bh);
    __nv_bfloat162 L = __halves2bfloat162(al, bl);
    hi = *(unsigned*)&H;
    lo = *(unsigned*)&L;
}

__device__ __forceinline__ void mma_bf16(float* d, const unsigned* a, const unsigned* b)
{
    asm("mma.sync.aligned.m16n8k16.row.col.f32.bf16.bf16.f32 "
        "{%0,%1,%2,%3}, {%4,%5,%6,%7}, {%8,%9}, {%0,%1,%2,%3};"
        : "+f"(d[0]), "+f"(d[1]), "+f"(d[2]), "+f"(d[3])
        : "r"(a[0]), "r"(a[1]), "r"(a[2]), "r"(a[3]), "r"(b[0]), "r"(b[1]));
}

// ---------------------------------------------------------------------------
// Kernel 1: support(fp16) = x @ W + lin_bias
// W (all 64 k-pairs) staged ONCE; x chunks register-prefetched (2-deep SW pipe).
// smem: ws 2*64*WS32 + xs 2*128*XS32 u32 = ~86 KB -> occ 2.
// ---------------------------------------------------------------------------
__global__ void __launch_bounds__(256, 2)
gemm_kernel(const float* __restrict__ x, const float* __restrict__ W,
            const float* __restrict__ lin_bias, __half* __restrict__ sup, int M)
{
    extern __shared__ unsigned sh[];
    unsigned* ws_hi = sh;                        // [64][WS32]
    unsigned* ws_lo = ws_hi + 64 * WS32;
    unsigned* xs_hi = ws_lo + 64 * WS32;         // [128][XS32]
    unsigned* xs_lo = xs_hi + 128 * XS32;

    const int tid  = threadIdx.x;
    const int warp = tid >> 5;
    const int lane = tid & 31;
    const int g    = lane >> 2;
    const int t4   = lane & 3;

    const int rowBase = blockIdx.x * 128;
    const int warpRow = (warp & 3) * 32;
    const int warpCol = (warp >> 2) * 64;

    // ---- stage ALL of W (64 k-pair rows) once ----
    for (int i = tid; i < 64 * (D / 4); i += 256) {
        int k2 = i >> 5;
        int n4 = (i & 31) * 4;
        float4 va = *(const float4*)(W + (size_t)(2 * k2)     * D + n4);
        float4 vb = *(const float4*)(W + (size_t)(2 * k2 + 1) * D + n4);
        uint4 ph, pl;
        split2_bf16(va.x, vb.x, ph.x, pl.x);
        split2_bf16(va.y, vb.y, ph.y, pl.y);
        split2_bf16(va.z, vb.z, ph.z, pl.z);
        split2_bf16(va.w, vb.w, ph.w, pl.w);
        *(uint4*)(ws_hi + k2 * WS32 + n4) = ph;
        *(uint4*)(ws_lo + k2 * WS32 + n4) = pl;
    }

    float acc[2][8][4];
#pragma unroll
    for (int mt = 0; mt < 2; mt++)
#pragma unroll
        for (int nt = 0; nt < 8; nt++)
#pragma unroll
            for (int i = 0; i < 4; i++) acc[mt][nt][i] = 0.f;

    // per-thread x-staging coords (4 float4 per chunk)
    int sm[4], skq[4];
#pragma unroll
    for (int j = 0; j < 4; j++) {
        int i = tid + j * 256;
        sm[j]  = i >> 3;
        skq[j] = (i & 7) * 4;
    }

    // prefetch chunk 0
    float4 pre[4];
#pragma unroll
    for (int j = 0; j < 4; j++) {
        int gm = rowBase + sm[j];
        pre[j] = (gm < M) ? *(const float4*)(x + (size_t)gm * D + skq[j])
                          : make_float4(0.f, 0.f, 0.f, 0.f);
    }

#pragma unroll
    for (int c = 0; c < 4; c++) {
        if (c) __syncthreads();           // previous compute done reading xs

        // store prefetched chunk into xs
#pragma unroll
        for (int j = 0; j < 4; j++) {
            unsigned h0, l0, h1, l1;
            split2_bf16(pre[j].x, pre[j].y, h0, l0);
            split2_bf16(pre[j].z, pre[j].w, h1, l1);
            *(uint2*)(xs_hi + sm[j] * XS32 + (skq[j] >> 1)) = make_uint2(h0, h1);
            *(uint2*)(xs_lo + sm[j] * XS32 + (skq[j] >> 1)) = make_uint2(l0, l1);
        }

        // prefetch next chunk (loads retire under the MMAs below)
        if (c < 3) {
            int k0n = (c + 1) * TK;
#pragma unroll
            for (int j = 0; j < 4; j++) {
                int gm = rowBase + sm[j];
                pre[j] = (gm < M) ? *(const float4*)(x + (size_t)gm * D + k0n + skq[j])
                                  : make_float4(0.f, 0.f, 0.f, 0.f);
            }
        }
        __syncthreads();

        const int kp0 = c * (TK / 2);     // global k-pair base of this chunk
#pragma unroll
        for (int ks2 = 0; ks2 < TK / 2; ks2 += 8) {
            unsigned bh[8][2], bl[8][2];
#pragma unroll
            for (int nt = 0; nt < 8; nt++) {
                int col = warpCol + nt * 8 + g;
                int kr  = kp0 + ks2 + t4;
                bh[nt][0] = ws_hi[kr       * WS32 + col];
                bh[nt][1] = ws_hi[(kr + 4) * WS32 + col];
                bl[nt][0] = ws_lo[kr       * WS32 + col];
                bl[nt][1] = ws_lo[(kr + 4) * WS32 + col];
            }
#pragma unroll
            for (int mt = 0; mt < 2; mt++) {
                int r0 = warpRow + mt * 16 + g;
                unsigned ah[4], al[4];
                ah[0] = xs_hi[r0       * XS32 + ks2 + t4];
                ah[1] = xs_hi[(r0 + 8) * XS32 + ks2 + t4];
                ah[2] = xs_hi[r0       * XS32 + ks2 + t4 + 4];
                ah[3] = xs_hi[(r0 + 8) * XS32 + ks2 + t4 + 4];
                al[0] = xs_lo[r0       * XS32 + ks2 + t4];
                al[1] = xs_lo[(r0 + 8) * XS32 + ks2 + t4];
                al[2] = xs_lo[r0       * XS32 + ks2 + t4 + 4];
                al[3] = xs_lo[(r0 + 8) * XS32 + ks2 + t4 + 4];
#pragma unroll
                for (int nt = 0; nt < 8; nt++) {
                    mma_bf16(acc[mt][nt], ah, bh[nt]);
                    mma_bf16(acc[mt][nt], ah, bl[nt]);
                    mma_bf16(acc[mt][nt], al, bh[nt]);
                }
            }
        }
    }

#pragma unroll
    for (int nt = 0; nt < 8; nt++) {
        int n = warpCol + nt * 8 + t4 * 2;
        float lb0 = lin_bias[n];
        float lb1 = lin_bias[n + 1];
#pragma unroll
        for (int mt = 0; mt < 2; mt++) {
            int gm0 = rowBase + warpRow + mt * 16 + g;
            int gm1 = gm0 + 8;
            if (gm0 < M)
                *(__half2*)(sup + (size_t)gm0 * D + n) =
                    __floats2half2_rn(acc[mt][nt][0] + lb0, acc[mt][nt][1] + lb1);
            if (gm1 < M)
                *(__half2*)(sup + (size_t)gm1 * D + n) =
                    __floats2half2_rn(acc[mt][nt][2] + lb0, acc[mt][nt][3] + lb1);
        }
    }
}

// ---------------------------------------------------------------------------
// CSR build
// ---------------------------------------------------------------------------
__global__ void hist_kernel(const int* __restrict__ rows, int* __restrict__ cnt, int nE)
{
    for (int e = blockIdx.x * blockDim.x + threadIdx.x; e < nE;
         e += gridDim.x * blockDim.x)
        atomicAdd(cnt + __ldg(rows + e), 1);
}

__global__ void scan1_kernel(int* __restrict__ data, int* __restrict__ bsums, int N)
{
    __shared__ int s[1024];
    int i = blockIdx.x * 1024 + threadIdx.x;
    int v = (i < N) ? data[i] : 0;
    s[threadIdx.x] = v;
    __syncthreads();
#pragma unroll
    for (int off = 1; off < 1024; off <<= 1) {
        int t = (threadIdx.x >= off) ? s[threadIdx.x - off] : 0;
        __syncthreads();
        s[threadIdx.x] += t;
        __syncthreads();
    }
    if (i < N) data[i] = s[threadIdx.x] - v;
    if (threadIdx.x == 1023) bsums[blockIdx.x] = s[1023];
}

// per-block prefix from raw bsums (warp reduction) — replaces scan2+scan3
__global__ void scan3_kernel(int* __restrict__ rowptr, int* __restrict__ cursor,
                             const int* __restrict__ bsums, int N, int nE)
{
    __shared__ int prefix;
    if (threadIdx.x < 32) {
        int sum = 0;
        for (int j = threadIdx.x; j < blockIdx.x; j += 32) sum += bsums[j];
#pragma unroll
        for (int off = 16; off > 0; off >>= 1)
            sum += __shfl_down_sync(0xffffffffu, sum, off);
        if (threadIdx.x == 0) prefix = sum;
    }
    __syncthreads();
    int i = blockIdx.x * 1024 + threadIdx.x;
    if (i < N) {
        int v = rowptr[i] + prefix;
        rowptr[i] = v;
        cursor[i] = v;
    }
    if (i == 0) rowptr[N] = nE;
}

__global__ void scatter_kernel(const int* __restrict__ rows, const int* __restrict__ cols,
                               const float* __restrict__ vals, int* __restrict__ cursor,
                               uint2* __restrict__ edges, int nE)
{
    for (int e = blockIdx.x * blockDim.x + threadIdx.x; e < nE;
         e += gridDim.x * blockDim.x) {
        int r = __ldg(rows + e);
        int p = atomicAdd(cursor + r, 1);
        edges[p] = make_uint2((unsigned)__ldg(cols + e),
                              __float_as_uint(__ldg(vals + e)));
    }
}

// ---------------------------------------------------------------------------
// CSR SpMM: warp per row, 4-edge unroll for MLP=4.
// ---------------------------------------------------------------------------
__device__ __forceinline__ void fma_edge(float4& acc, uint2 q, float v)
{
    float2 a = __half22float2(*(__half2*)&q.x);
    float2 b = __half22float2(*(__half2*)&q.y);
    acc.x = fmaf(a.x, v, acc.x); acc.y = fmaf(a.y, v, acc.y);
    acc.z = fmaf(b.x, v, acc.z); acc.w = fmaf(b.y, v, acc.w);
}

__global__ void __launch_bounds__(256)
csr_kernel(const __half* __restrict__ sup, const uint2* __restrict__ edges,
           const int* __restrict__ rowptr, const float* __restrict__ bias,
           float* __restrict__ out, int N)
{
    int r = blockIdx.x * 8 + (threadIdx.x >> 5);
    if (r >= N) return;
    int lane = threadIdx.x & 31;

    int s = __ldg(rowptr + r);
    int e = __ldg(rowptr + r + 1);

    float4 acc = *(const float4*)(bias + lane * 4);

    int i = s;
    for (; i + 3 < e; i += 4) {
        uint2 ev0 = __ldg(edges + i);
        uint2 ev1 = __ldg(edges + i + 1);
        uint2 ev2 = __ldg(edges + i + 2);
        uint2 ev3 = __ldg(edges + i + 3);
        uint2 q0 = *(const uint2*)(sup + (size_t)ev0.x * D + lane * 4);
        uint2 q1 = *(const uint2*)(sup + (size_t)ev1.x * D + lane * 4);
        uint2 q2 = *(const uint2*)(sup + (size_t)ev2.x * D + lane * 4);
        uint2 q3 = *(const uint2*)(sup + (size_t)ev3.x * D + lane * 4);
        fma_edge(acc, q0, __uint_as_float(ev0.y));
        fma_edge(acc, q1, __uint_as_float(ev1.y));
        fma_edge(acc, q2, __uint_as_float(ev2.y));
        fma_edge(acc, q3, __uint_as_float(ev3.y));
    }
    for (; i < e; i++) {
        uint2 ev = __ldg(edges + i);
        uint2 q = *(const uint2*)(sup + (size_t)ev.x * D + lane * 4);
        fma_edge(acc, q, __uint_as_float(ev.y));
    }

    *(float4*)(out + (size_t)r * D + lane * 4) = acc;
}

// ---------------------------------------------------------------------------
extern "C" void kernel_launch(void* const* d_in, const int* in_sizes, int n_in,
                              void* d_out, int out_size)
{
    const float* x        = (const float*)d_in[0];
    const float* W        = (const float*)d_in[1];
    const float* lin_bias = (const float*)d_in[2];
    const float* bias     = (const float*)d_in[3];
    const int*   adj_rows = (const int*)d_in[4];
    const int*   adj_cols = (const int*)d_in[5];
    const float* adj_vals = (const float*)d_in[6];
    float* out = (float*)d_out;

    const int M  = in_sizes[0] / D;      // 100000
    const int nE = in_sizes[4];          // 1600000

    __half* sup = nullptr;   cudaGetSymbolAddress((void**)&sup, g_support);
    int* rowptr = nullptr;   cudaGetSymbolAddress((void**)&rowptr, g_rowptr);
    int* cursor = nullptr;   cudaGetSymbolAddress((void**)&cursor, g_cursor);
    int* bsums  = nullptr;   cudaGetSymbolAddress((void**)&bsums, g_bsums);
    uint2* edges = nullptr;  cudaGetSymbolAddress((void**)&edges, g_edges);

    const int smem = (2 * 64 * WS32 + 2 * 128 * XS32) * sizeof(unsigned); // ~86 KB
    cudaFuncSetAttribute(gemm_kernel, cudaFuncAttributeMaxDynamicSharedMemorySize, smem);

    const int NB = (M + 1023) / 1024;    // 98

    cudaMemsetAsync(rowptr, 0, (M + 1) * sizeof(int));
    hist_kernel<<<256, 256>>>(adj_rows, rowptr, nE);

    gemm_kernel<<<(M + 127) / 128, 256, smem>>>(x, W, lin_bias, sup, M);

    scan1_kernel<<<NB, 1024>>>(rowptr, bsums, M);
    scan3_kernel<<<NB, 1024>>>(rowptr, cursor, bsums, M, nE);
    scatter_kernel<<<256, 256>>>(adj_rows, adj_cols, adj_vals, cursor, edges, nE);

    csr_kernel<<<(M + 7) / 8, 256>>>(sup, edges, rowptr, bias, out, M);
}